// round 9
// baseline (speedup 1.0000x reference)
#include <cuda_runtime.h>
#include <cuda_fp16.h>
#include <cstdint>

// ---------------- problem constants ----------------
constexpr int B    = 2;
constexpr int N    = 6400;
constexpr int E    = 256;
constexpr int CAMS = 6;
constexpr int LVLS = 4;
constexpr int BN_PTS = B * N;          // 12800
__device__ constexpr int HGT[LVLS]  = {64, 32, 16, 8};
__device__ constexpr int WID[LVLS]  = {176, 88, 44, 22};
__device__ constexpr int LOFF[LVLS] = {0, 11264, 14080, 14784};
constexpr int TOTHW = 14960;           // sum of H*W

// ---------------- device scratch (no runtime alloc allowed) ----------------
__device__ __half g_featT[(size_t)B * CAMS * TOTHW * E];  // ~92 MB, [b,c,hw,E] fp16
__device__ __half g_aggH[(size_t)BN_PTS * E];             // aggregation (fp16)
__device__ __half g_xh[(size_t)BN_PTS * E];               // after vp GEMM + residual
__device__ __half g_vpH[E * E];
__device__ __half g_opH[E * E];

// ---------------- helpers ----------------
__device__ __forceinline__ uint32_t smem_u32(const void* p) {
    return (uint32_t)__cvta_generic_to_shared(p);
}
__device__ __forceinline__ void ldmx4(unsigned r[4], uint32_t addr) {
    asm volatile("ldmatrix.sync.aligned.m8n8.x4.shared.b16 {%0,%1,%2,%3}, [%4];"
                 : "=r"(r[0]), "=r"(r[1]), "=r"(r[2]), "=r"(r[3]) : "r"(addr));
}
__device__ __forceinline__ void mma16816(float d[4], const unsigned a[4], const unsigned b[2]) {
    asm volatile("mma.sync.aligned.m16n8k16.row.col.f32.f16.f16.f32 "
                 "{%0,%1,%2,%3}, {%4,%5,%6,%7}, {%8,%9}, {%0,%1,%2,%3};"
                 : "+f"(d[0]), "+f"(d[1]), "+f"(d[2]), "+f"(d[3])
                 : "r"(a[0]), "r"(a[1]), "r"(a[2]), "r"(a[3]), "r"(b[0]), "r"(b[1]));
}

// ---------------- 0) weight fp32 -> fp16 ----------------
__global__ __launch_bounds__(256) void convert_w_kernel(const float* __restrict__ vp,
                                                        const float* __restrict__ op) {
    int i = blockIdx.x * 256 + threadIdx.x;    // 65536 threads
    g_vpH[i] = __float2half(vp[i]);
    g_opH[i] = __float2half(op[i]);
}

// ---------------- 1) feature transpose: [b,c,E,HW] -> [b,c,HW,E] fp16 ------
// 64x64 tiles over flattened HW; float4 reads, uint4 (16B fp16) writes.
template <int L>
__global__ __launch_bounds__(256) void transpose_kernel(const float* __restrict__ src0) {
    constexpr int H  = (L == 0 ? 64 : L == 1 ? 32 : L == 2 ? 16 : 8);
    constexpr int W  = (L == 0 ? 176 : L == 1 ? 88 : L == 2 ? 44 : 22);
    constexpr int HW = H * W;
    constexpr int OFF = (L == 0 ? 0 : L == 1 ? 11264 : L == 2 ? 14080 : 14784);

    int bc  = blockIdx.z;                 // 0..11
    int hw0 = blockIdx.x * 64;
    int e0  = blockIdx.y * 64;
    int t   = threadIdx.x;

    const float* src = src0 + (size_t)bc * E * HW;
    __half* dst = g_featT + ((size_t)bc * TOTHW + OFF) * E;

    __shared__ float tile[64][65];        // [e][hw]

    #pragma unroll
    for (int i = 0; i < 4; i++) {
        int idx = t + i * 256;            // 0..1023
        int er  = idx >> 4;               // e row 0..63
        int c4  = idx & 15;               // float4 col
        int hw  = hw0 + c4 * 4;
        if (hw < HW) {
            float4 v = *(const float4*)(src + (size_t)(e0 + er) * HW + hw);
            tile[er][c4 * 4 + 0] = v.x;
            tile[er][c4 * 4 + 1] = v.y;
            tile[er][c4 * 4 + 2] = v.z;
            tile[er][c4 * 4 + 3] = v.w;
        }
    }
    __syncthreads();

    #pragma unroll
    for (int i = 0; i < 2; i++) {
        int idx = t + i * 256;            // 0..511
        int hwl = idx >> 3;               // hw row 0..63
        int seg = idx & 7;                // e segment of 8 halves
        int hw  = hw0 + hwl;
        if (hw < HW) {
            __half2 v0 = __floats2half2_rn(tile[seg * 8 + 0][hwl], tile[seg * 8 + 1][hwl]);
            __half2 v1 = __floats2half2_rn(tile[seg * 8 + 2][hwl], tile[seg * 8 + 3][hwl]);
            __half2 v2 = __floats2half2_rn(tile[seg * 8 + 4][hwl], tile[seg * 8 + 5][hwl]);
            __half2 v3 = __floats2half2_rn(tile[seg * 8 + 6][hwl], tile[seg * 8 + 7][hwl]);
            uint4 pk;
            pk.x = *(const unsigned*)&v0;
            pk.y = *(const unsigned*)&v1;
            pk.z = *(const unsigned*)&v2;
            pk.w = *(const unsigned*)&v3;
            *(uint4*)(dst + (size_t)hw * E + e0 + seg * 8) = pk;
        }
    }
}

// ---------------- 2+3) fused prep + bilinear gather/aggregate --------------
// 8 points per block, one warp per point. Warp computes attn softmax + uv
// into its private smem slice, then gathers fp16 features (8 ch/lane).
__global__ __launch_bounds__(256) void aggregate_kernel(
                            const float* __restrict__ instf,
                            const float* __restrict__ anchor,
                            const float* __restrict__ proj,
                            const float* __restrict__ attn_w,
                            const float* __restrict__ attn_b) {
    int t    = threadIdx.x;
    int pt   = t >> 5;                // warp / point-within-block
    int lane = t & 31;
    int p    = blockIdx.x * 8 + pt;
    int b    = p / N;

    __shared__ float s_attn[8][24];
    __shared__ float s_uv[8][14];

    // ---- prep phase (per warp) ----
    {
        const float* ifp = instf + (size_t)p * E;
        float v[8];
        #pragma unroll
        for (int k = 0; k < 8; k++) v[k] = ifp[k * 32 + lane];

        float logit[24];
        #pragma unroll
        for (int cl = 0; cl < 24; cl++) {
            const float* w = attn_w + cl * E;
            float s = 0.f;
            #pragma unroll
            for (int k = 0; k < 8; k++) s = fmaf(v[k], w[k * 32 + lane], s);
            #pragma unroll
            for (int o = 16; o; o >>= 1) s += __shfl_xor_sync(0xffffffffu, s, o);
            logit[cl] = s + attn_b[cl];
        }

        if (lane == 0) {
            #pragma unroll
            for (int c = 0; c < CAMS; c++) {
                float l0 = logit[c * 4 + 0], l1 = logit[c * 4 + 1];
                float l2 = logit[c * 4 + 2], l3 = logit[c * 4 + 3];
                float mx = fmaxf(fmaxf(l0, l1), fmaxf(l2, l3));
                float e0 = expf(l0 - mx), e1 = expf(l1 - mx);
                float e2 = expf(l2 - mx), e3 = expf(l3 - mx);
                float inv = 1.0f / (e0 + e1 + e2 + e3);
                s_attn[pt][c * 4 + 0] = e0 * inv;
                s_attn[pt][c * 4 + 1] = e1 * inv;
                s_attn[pt][c * 4 + 2] = e2 * inv;
                s_attn[pt][c * 4 + 3] = e3 * inv;
            }
        }

        float ax = anchor[(size_t)p * 11 + 0];
        float ay = anchor[(size_t)p * 11 + 1];
        float az = anchor[(size_t)p * 11 + 2];
        float sx = 1.0f / (1.0f + expf(-ax));
        float sy = 1.0f / (1.0f + expf(-ay));
        float sz = 1.0f / (1.0f + expf(-az));
        float X = sx * 102.4f - 51.2f;
        float Y = sy * 102.4f - 51.2f;
        float Z = sz * 8.0f   - 5.0f;

        if (lane < CAMS) {
            const float* P = proj + ((size_t)b * CAMS + lane) * 16;
            float c0 = P[0]  * X + P[1]  * Y + P[2]  * Z + P[3];
            float c1 = P[4]  * X + P[5]  * Y + P[6]  * Z + P[7];
            float c2 = P[8]  * X + P[9]  * Y + P[10] * Z + P[11];
            float d  = fmaxf(c2, 0.0001f);
            s_uv[pt][lane * 2 + 0] = c0 / d;
            s_uv[pt][lane * 2 + 1] = c1 / d;
        }
        __syncwarp();
    }

    // ---- gather/aggregate phase ----
    float acc[8] = {0.f, 0.f, 0.f, 0.f, 0.f, 0.f, 0.f, 0.f};

    #pragma unroll
    for (int c = 0; c < CAMS; c++) {
        float x = s_uv[pt][c * 2 + 0];
        float y = s_uv[pt][c * 2 + 1];
        float x0 = floorf(x), y0 = floorf(y);
        float wx1 = x - x0, wx0 = 1.0f - wx1;
        float wy1 = y - y0, wy0 = 1.0f - wy1;
        const __half* base = g_featT + ((size_t)b * CAMS + c) * TOTHW * E;
        #pragma unroll
        for (int l = 0; l < LVLS; l++) {
            const int Wl = WID[l], Hl = HGT[l], off = LOFF[l];
            float wa = s_attn[pt][c * 4 + l];
            #pragma unroll
            for (int cy = 0; cy < 2; cy++) {
                float yf = y0 + cy;
                float wy = cy ? wy1 : wy0;
                if (yf < 0.f || yf > (float)(Hl - 1)) continue;
                #pragma unroll
                for (int cx = 0; cx < 2; cx++) {
                    float xf = x0 + cx;
                    float wx = cx ? wx1 : wx0;
                    if (xf < 0.f || xf > (float)(Wl - 1)) continue;
                    float wgt = wa * wx * wy;
                    int xi = (int)xf, yi = (int)yf;
                    const __half* fp = base + ((size_t)(off + yi * Wl + xi)) * E + lane * 8;
                    uint4 raw = *(const uint4*)fp;
                    const __half2* h2 = (const __half2*)&raw;
                    #pragma unroll
                    for (int q = 0; q < 4; q++) {
                        float2 f = __half22float2(h2[q]);
                        acc[q * 2 + 0] = fmaf(wgt, f.x, acc[q * 2 + 0]);
                        acc[q * 2 + 1] = fmaf(wgt, f.y, acc[q * 2 + 1]);
                    }
                }
            }
        }
    }
    __half2 o0 = __floats2half2_rn(acc[0], acc[1]);
    __half2 o1 = __floats2half2_rn(acc[2], acc[3]);
    __half2 o2 = __floats2half2_rn(acc[4], acc[5]);
    __half2 o3 = __floats2half2_rn(acc[6], acc[7]);
    uint4 pk;
    pk.x = *(const unsigned*)&o0; pk.y = *(const unsigned*)&o1;
    pk.z = *(const unsigned*)&o2; pk.w = *(const unsigned*)&o3;
    *(uint4*)(g_aggH + (size_t)p * E + lane * 8) = pk;
}

// ---------------- 4) fp16 tensor-core NT-GEMM --------------------------------
// MODE 0: A=g_aggH, W=g_vpH,  out = half(acc + vp_b[n] + instf[m][n]) -> g_xh
// MODE 1: A=g_xh,   W=g_opH,  out = float(acc + op_b[n])              -> Cout
template <int MODE>
__global__ __launch_bounds__(256) void gemm_h_kernel(
        const float* __restrict__ bias,
        const float* __restrict__ instf,
        float* __restrict__ Cout) {
    constexpr int K = 256;
    const __half* A = (MODE == 0) ? g_aggH : g_xh;
    const __half* W = (MODE == 0) ? g_vpH  : g_opH;

    __shared__ __half sA[128 * 64];
    __shared__ __half sB[64 * 64];

    int bm = blockIdx.x * 128;
    int bn = blockIdx.y * 64;
    int t  = threadIdx.x;
    int warp = t >> 5, lane = t & 31;
    int wm = warp >> 1, wn = warp & 1;

    auto swz = [](int row, int chunk) { return row * 64 + ((chunk ^ (row & 7)) << 3); };

    float acc[2][4][4];
    #pragma unroll
    for (int i = 0; i < 2; i++)
        #pragma unroll
        for (int j = 0; j < 4; j++)
            #pragma unroll
            for (int q = 0; q < 4; q++) acc[i][j][q] = 0.f;

    int lidx = lane & 7, lg = lane >> 3;

    for (int k0 = 0; k0 < K; k0 += 64) {
        #pragma unroll
        for (int i = 0; i < 4; i++) {
            int cchunk = t + i * 256;
            int row = cchunk >> 3, ch = cchunk & 7;
            uint4 v = *(const uint4*)(A + (size_t)(bm + row) * K + k0 + ch * 8);
            *(uint4*)(sA + swz(row, ch)) = v;
        }
        #pragma unroll
        for (int i = 0; i < 2; i++) {
            int cchunk = t + i * 256;
            int row = cchunk >> 3, ch = cchunk & 7;
            uint4 v = *(const uint4*)(W + (size_t)(bn + row) * K + k0 + ch * 8);
            *(uint4*)(sB + swz(row, ch)) = v;
        }
        __syncthreads();

        #pragma unroll
        for (int ks = 0; ks < 4; ks++) {
            int kc = ks * 2;
            unsigned af[2][4], bf[2][4];
            #pragma unroll
            for (int mt = 0; mt < 2; mt++) {
                int row = wm * 32 + mt * 16 + (lg & 1) * 8 + lidx;
                int ch  = kc + (lg >> 1);
                ldmx4(af[mt], smem_u32(sA + swz(row, ch)));
            }
            #pragma unroll
            for (int h = 0; h < 2; h++) {
                int row = wn * 32 + h * 16 + ((lg >> 1) & 1) * 8 + lidx;
                int ch  = kc + (lg & 1);
                ldmx4(bf[h], smem_u32(sB + swz(row, ch)));
            }
            #pragma unroll
            for (int mt = 0; mt < 2; mt++)
                #pragma unroll
                for (int nt = 0; nt < 4; nt++)
                    mma16816(acc[mt][nt], af[mt], bf[nt >> 1] + (nt & 1) * 2);
        }
        __syncthreads();
    }

    int rbase = bm + wm * 32 + (lane >> 2);
    int cbase = bn + wn * 32 + (lane & 3) * 2;
    #pragma unroll
    for (int mt = 0; mt < 2; mt++) {
        #pragma unroll
        for (int nt = 0; nt < 4; nt++) {
            int col = cbase + nt * 8;
            float b0 = bias[col], b1 = bias[col + 1];
            #pragma unroll
            for (int h = 0; h < 2; h++) {
                int row = rbase + mt * 16 + h * 8;
                float v0 = acc[mt][nt][h * 2 + 0] + b0;
                float v1 = acc[mt][nt][h * 2 + 1] + b1;
                if (MODE == 0) {
                    v0 += instf[(size_t)row * 256 + col];
                    v1 += instf[(size_t)row * 256 + col + 1];
                    __half2 hv = __floats2half2_rn(v0, v1);
                    *(__half2*)(g_xh + (size_t)row * 256 + col) = hv;
                } else {
                    *(float2*)(Cout + (size_t)row * 256 + col) = make_float2(v0, v1);
                }
            }
        }
    }
}

// ---------------- launch ----------------
extern "C" void kernel_launch(void* const* d_in, const int* in_sizes, int n_in,
                              void* d_out, int out_size) {
    const float* instf  = (const float*)d_in[0];
    const float* anchor = (const float*)d_in[1];
    const float* proj   = (const float*)d_in[2];
    const float* f0     = (const float*)d_in[3];
    const float* f1     = (const float*)d_in[4];
    const float* f2     = (const float*)d_in[5];
    const float* f3     = (const float*)d_in[6];
    const float* attn_w = (const float*)d_in[7];
    const float* attn_b = (const float*)d_in[8];
    const float* vp_w   = (const float*)d_in[9];
    const float* vp_b   = (const float*)d_in[10];
    const float* op_w   = (const float*)d_in[11];
    const float* op_b   = (const float*)d_in[12];
    float* out = (float*)d_out;

    convert_w_kernel<<<256, 256>>>(vp_w, op_w);

    // transpose: 64x64 tiles over flattened HW
    transpose_kernel<0><<<dim3(176, 4, B * CAMS), 256>>>(f0);  // HW=11264
    transpose_kernel<1><<<dim3(44,  4, B * CAMS), 256>>>(f1);  // HW=2816
    transpose_kernel<2><<<dim3(11,  4, B * CAMS), 256>>>(f2);  // HW=704
    transpose_kernel<3><<<dim3(3,   4, B * CAMS), 256>>>(f3);  // HW=176

    // fused prep + aggregate
    aggregate_kernel<<<BN_PTS / 8, 256>>>(instf, anchor, proj, attn_w, attn_b);

    dim3 gg(BN_PTS / 128, 256 / 64);
    gemm_h_kernel<0><<<gg, 256>>>(vp_b, instf, out);
    gemm_h_kernel<1><<<gg, 256>>>(op_b, nullptr, out);
}